// round 16
// baseline (speedup 1.0000x reference)
#include <cuda_runtime.h>
#include <cstdint>

#define B_  8
#define C_  64
#define H_  64
#define W_  64
#define NN  9
#define M_  18
#define HP  66
#define KTOT 576

typedef unsigned long long ull;

__device__ float g_off4[4][B_ * M_ * H_ * W_];   // k1 4-way split-k partials
__device__ float g_Wp[KTOT * C_];                // [(n*64+ci)*64 + co]
__device__ float g_xt[B_ * H_ * W_ * C_];        // x transposed: [b][h][w][ci]
__device__ float g_part[2][B_ * C_ * H_ * W_];   // k2 split-K partials

// ---------------- helpers ----------------
__device__ __forceinline__ void ffma2(ull& d, ull a, ull b) {
    asm("fma.rn.f32x2 %0, %1, %2, %0;" : "+l"(d) : "l"(a), "l"(b));
}
__device__ __forceinline__ float2 unpack2(ull v) {
    float2 r; asm("mov.b64 {%0, %1}, %2;" : "=f"(r.x), "=f"(r.y) : "l"(v)); return r;
}
__device__ __forceinline__ ull dup2(float v) {
    ull r; asm("mov.b64 %0, {%1, %1};" : "=l"(r) : "f"(v)); return r;
}
__device__ __forceinline__ ull pack2(float lo, float hi) {
    ull r; asm("mov.b64 %0, {%1, %2};" : "=l"(r) : "f"(lo), "f"(hi)); return r;
}

// ---------------------------------------------------------------------------
// K1: offset conv 2px/thread, 4-way ci split (z=0..31: b*4+q).
// z==32: prep g_Wp.  z=33..40: transpose x -> g_xt for batch z-33.
// ---------------------------------------------------------------------------
#define CI_Q 16
#define K1_SMEM ((CI_Q*612 + CI_Q*9*10*2) * 4)   // 50688 B

__global__ __launch_bounds__(256, 2)
void k1_offset_conv(const float* __restrict__ x,
                    const float* __restrict__ Woff,
                    const float* __restrict__ boff,
                    const float* __restrict__ Wc) {
    const int tid = threadIdx.x;

    if (blockIdx.z == 32) {      // prep permuted GEMM weights
        int base = (blockIdx.y * 2 + blockIdx.x) * 256 + tid;
        for (int i = base; i < KTOT * C_; i += 8 * 256) {
            int kp = i >> 6;
            int co = i & 63;
            int n  = kp >> 6;
            int ci = kp & 63;
            g_Wp[i] = Wc[co * KTOT + ci * 9 + n];
        }
        return;
    }
    if (blockIdx.z >= 33) {      // transpose x[b][ci][h][w] -> g_xt[b][h][w][ci]
        extern __shared__ float smemT[];
        float* tile = smemT;     // [64 ci][65]
        const int b  = blockIdx.z - 33;
        const int h0 = (blockIdx.y * 2 + blockIdx.x) * 8;
        for (int hh = 0; hh < 8; hh++) {
            int h = h0 + hh;
#pragma unroll
            for (int j = 0; j < 16; j++) {
                int idx = j * 256 + tid;
                int ci = idx >> 6, w = idx & 63;
                tile[ci * 65 + w] = x[(((size_t)b * C_ + ci) * H_ + h) * W_ + w];
            }
            __syncthreads();
            float4* dst = (float4*)(g_xt + (((size_t)b * H_ + h) * W_) * C_);
#pragma unroll
            for (int j = 0; j < 4; j++) {
                int idx = j * 256 + tid;
                int w = idx >> 4, c4 = idx & 15;
                dst[w * 16 + c4] = make_float4(tile[(c4 * 4 + 0) * 65 + w],
                                               tile[(c4 * 4 + 1) * 65 + w],
                                               tile[(c4 * 4 + 2) * 65 + w],
                                               tile[(c4 * 4 + 3) * 65 + w]);
            }
            __syncthreads();
        }
        return;
    }

    extern __shared__ float smem[];
    float*  xs  = smem;                          // [cil][18][34]
    float2* ws2 = (float2*)(smem + CI_Q * 612);  // [cil][9][10]

    const int b   = blockIdx.z >> 2;
    const int qf  = blockIdx.z & 3;
    const int ci0 = qf * CI_Q;
    const int th0 = blockIdx.y * 16;
    const int tw0 = blockIdx.x * 32;

    const float* xb = x + (size_t)b * C_ * H_ * W_;
    for (int idx = tid; idx < CI_Q * 612; idx += 256) {
        int cil = idx / 612;
        int rem = idx % 612;
        int r = rem / 34, c = rem % 34;
        int gh = th0 + r - 1, gw = tw0 + c - 1;
        float v = 0.f;
        if ((unsigned)gh < H_ && (unsigned)gw < W_)
            v = xb[((ci0 + cil) * H_ + gh) * W_ + gw];
        xs[idx] = v;
    }
    for (int idx = tid; idx < CI_Q * 81; idx += 256) {
        int cil = idx / 81;
        int rem = idx % 81;
        int j = rem / 9, t = rem % 9;
        int ci = ci0 + cil;
        ws2[(cil * 9 + j) * 10 + t] =
            make_float2(Woff[(2 * j)     * 576 + ci * 9 + t],
                        Woff[(2 * j + 1) * 576 + ci * 9 + t]);
    }
    __syncthreads();

    const int lh = tid >> 4;
    const int lw = tid & 15;
    ull acc[9][2];
#pragma unroll
    for (int j = 0; j < 9; j++) {
        ull init = (qf == 0) ? pack2(boff[2 * j], boff[2 * j + 1]) : 0ull;
        acc[j][0] = init;
        acc[j][1] = init;
    }

    for (int cil = 0; cil < CI_Q; cil++) {
        ull d[3][4];
        const float* xc = xs + cil * 612 + lh * 34 + 2 * lw;
#pragma unroll
        for (int u = 0; u < 3; u++) {
            float2 A = *(const float2*)(xc + u * 34);
            float2 Bv = *(const float2*)(xc + u * 34 + 2);
            d[u][0] = dup2(A.x);
            d[u][1] = dup2(A.y);
            d[u][2] = dup2(Bv.x);
            d[u][3] = dup2(Bv.y);
        }
#pragma unroll
        for (int j = 0; j < 9; j++) {
            const ulonglong2* wp = (const ulonglong2*)(ws2 + (cil * 9 + j) * 10);
            ulonglong2 wA = wp[0];
            ulonglong2 wB = wp[1];
            ulonglong2 wC = wp[2];
            ulonglong2 wD = wp[3];
            ull        wE = *(const ull*)(ws2 + (cil * 9 + j) * 10 + 8);
            ffma2(acc[j][0], wA.x, d[0][0]); ffma2(acc[j][1], wA.x, d[0][1]);
            ffma2(acc[j][0], wA.y, d[0][1]); ffma2(acc[j][1], wA.y, d[0][2]);
            ffma2(acc[j][0], wB.x, d[0][2]); ffma2(acc[j][1], wB.x, d[0][3]);
            ffma2(acc[j][0], wB.y, d[1][0]); ffma2(acc[j][1], wB.y, d[1][1]);
            ffma2(acc[j][0], wC.x, d[1][1]); ffma2(acc[j][1], wC.x, d[1][2]);
            ffma2(acc[j][0], wC.y, d[1][2]); ffma2(acc[j][1], wC.y, d[1][3]);
            ffma2(acc[j][0], wD.x, d[2][0]); ffma2(acc[j][1], wD.x, d[2][1]);
            ffma2(acc[j][0], wD.y, d[2][1]); ffma2(acc[j][1], wD.y, d[2][2]);
            ffma2(acc[j][0], wE,   d[2][2]); ffma2(acc[j][1], wE,   d[2][3]);
        }
    }

    const int h = th0 + lh, w0 = tw0 + 2 * lw;
    float* dst = g_off4[qf];
#pragma unroll
    for (int j = 0; j < 9; j++) {
        float2 p0 = unpack2(acc[j][0]);
        float2 p1 = unpack2(acc[j][1]);
        *(float2*)&dst[((b * M_ + 2 * j)     * H_ + h) * W_ + w0] = make_float2(p0.x, p1.x);
        *(float2*)&dst[((b * M_ + 2 * j + 1) * H_ + h) * W_ + w0] = make_float2(p0.y, p1.y);
    }
}

// ---------------------------------------------------------------------------
// K2: transposed-x gather (1 wf per corner warp-LDG) + GEMM, split-K (z=2).
// Block = (b, 1 row, kz): chunks gc = 9kz..9kz+8 (n in [4kz,4kz+4]).
// xo rows padded to 68 floats. Partials -> g_part[kz].
// ---------------------------------------------------------------------------
#define CK    32
#define XROW  68
#define NLOC  5
#define NSAMP_H (NLOC * 64)                      // 320
#define SM_Q  0                                  // ushort4[320] = 2560
#define SM_G  (SM_Q + NSAMP_H * 8)               // float4[320]  = 5120
#define SM_XO (SM_G + NSAMP_H * 16)              // [32][68] = 8704
#define SM_W  (SM_XO + CK * XROW * 4)            // [32][64] = 8192
#define K2_SMEM (SM_W + CK * 64 * 4)             // 24576

__global__ __launch_bounds__(128, 5)
void k2_sample_gemm() {
    extern __shared__ char smc[];
    ushort4* s_q  = (ushort4*)(smc + SM_Q);
    float4*  s_g  = (float4*)(smc + SM_G);
    float*   xo_s = (float*)(smc + SM_XO);
    float*   w_s  = (float*)(smc + SM_W);

    const int tid = threadIdx.x;
    const int h   = blockIdx.x;
    const int b   = blockIdx.y;
    const int kz  = blockIdx.z;
    const int nb  = 4 * kz;

    // ---- Phase A: meta for 5 local n ---------------------------------------
    for (int t = tid; t < NSAMP_H; t += 128) {
        int n  = nb + (t >> 6);
        int px = t & 63;
        int ixi = ((b * M_ + n)     * H_ + h) * W_ + px;
        int iyi = ((b * M_ + 9 + n) * H_ + h) * W_ + px;
        float offx = (g_off4[0][ixi] + g_off4[1][ixi])
                   + (g_off4[2][ixi] + g_off4[3][ixi]);
        float offy = (g_off4[0][iyi] + g_off4[1][iyi])
                   + (g_off4[2][iyi] + g_off4[3][iyi]);
        float pX = (float)(h + 1)  + (float)(n / 3 - 1) + offx;
        float pY = (float)(px + 1) + (float)(n % 3 - 1) + offy;
        float fx = floorf(pX), fy = floorf(pY);
        int x0 = min(max((int)fx,     0), HP - 1);
        int x1 = min(max((int)fx + 1, 0), HP - 1);
        int y0 = min(max((int)fy,     0), HP - 1);
        int y1 = min(max((int)fy + 1, 0), HP - 1);
        float pxc = fminf(fmaxf(pX, 0.f), (float)(HP - 1));
        float pyc = fminf(fmaxf(pY, 0.f), (float)(HP - 1));
        float gx0 = 1.f + ((float)x0 - pxc);
        float gx1 = 1.f - ((float)x1 - pxc);
        float gy0 = 1.f + ((float)y0 - pyc);
        float gy1 = 1.f - ((float)y1 - pyc);
        int ix0 = x0 - 1, iy0 = y0 - 1, ix1 = x1 - 1, iy1 = y1 - 1;
        bool vx0 = (unsigned)ix0 < H_, vy0 = (unsigned)iy0 < W_;
        bool vx1 = (unsigned)ix1 < H_, vy1 = (unsigned)iy1 < W_;
        int cx0 = min(max(ix0, 0), H_ - 1);
        int cx1 = min(max(ix1, 0), H_ - 1);
        int cy0 = min(max(iy0, 0), W_ - 1);
        int cy1 = min(max(iy1, 0), W_ - 1);
        s_q[t] = make_ushort4((unsigned short)((cx0 << 6) + cy0),
                              (unsigned short)((cx1 << 6) + cy1),
                              (unsigned short)((cx0 << 6) + cy1),
                              (unsigned short)((cx1 << 6) + cy0));
        s_g[t] = make_float4(vx0 && vy0 ? gx0 * gy0 : 0.f,
                             vx1 && vy1 ? gx1 * gy1 : 0.f,
                             vx0 && vy1 ? gx0 * gy1 : 0.f,
                             vx1 && vy0 ? gx1 * gy0 : 0.f);
    }

    const int wi   = tid >> 5;        // warp 0..3
    const int lane = tid & 31;        // gather ci lane
    const int pg   = tid >> 4;        // GEMM: 8 groups x 8 px
    const int cg   = tid & 15;        // GEMM: 16 groups x 4 co
    const float* xtb = g_xt + (size_t)b * (H_ * W_ * C_);

    ull acc[4][4];
#pragma unroll
    for (int i = 0; i < 4; i++)
#pragma unroll
        for (int j = 0; j < 4; j++) acc[i][j] = 0ull;

    for (int cc = 0; cc < 9; cc++) {
        const int gc  = kz * 9 + cc;
        const int ln  = (gc >> 1) - nb;
        const int ci0 = (gc & 1) * 32;
        __syncthreads();

        // B chunk
        {
            const float4* src = (const float4*)(g_Wp + gc * (CK * 64));
            float4* dst = (float4*)w_s;
#pragma unroll
            for (int j = 0; j < 4; j++)
                dst[j * 128 + tid] = src[j * 128 + tid];
        }

        // gather: warp = (1 px, 32 ci) per iter; each corner = 1 line
#pragma unroll 2
        for (int it = 0; it < 16; it++) {
            int px = it * 4 + wi;
            ushort4 q = s_q[ln * 64 + px];
            float4  g = s_g[ln * 64 + px];
            int cbase = ci0 + lane;
            float v = g.x * __ldg(xtb + (((int)q.x) << 6) + cbase)
                    + g.y * __ldg(xtb + (((int)q.y) << 6) + cbase)
                    + g.z * __ldg(xtb + (((int)q.z) << 6) + cbase)
                    + g.w * __ldg(xtb + (((int)q.w) << 6) + cbase);
            xo_s[lane * XROW + px] = v;
        }
        __syncthreads();

        // GEMM chunk: 32 kk, 16 FFMA2/kk
#pragma unroll 4
        for (int kk = 0; kk < CK; kk++) {
            float4 a0 = *(const float4*)&xo_s[kk * XROW + pg * 8];
            float4 a1 = *(const float4*)&xo_s[kk * XROW + pg * 8 + 4];
            float4 w  = *(const float4*)&w_s[kk * 64 + cg * 4];
            ull a01 = ((const ull*)&a0)[0];
            ull a23 = ((const ull*)&a0)[1];
            ull a45 = ((const ull*)&a1)[0];
            ull a67 = ((const ull*)&a1)[1];
            ull w0 = dup2(w.x), w1 = dup2(w.y), w2 = dup2(w.z), w3 = dup2(w.w);
            ffma2(acc[0][0], w0, a01); ffma2(acc[0][1], w0, a23);
            ffma2(acc[0][2], w0, a45); ffma2(acc[0][3], w0, a67);
            ffma2(acc[1][0], w1, a01); ffma2(acc[1][1], w1, a23);
            ffma2(acc[1][2], w1, a45); ffma2(acc[1][3], w1, a67);
            ffma2(acc[2][0], w2, a01); ffma2(acc[2][1], w2, a23);
            ffma2(acc[2][2], w2, a45); ffma2(acc[2][3], w2, a67);
            ffma2(acc[3][0], w3, a01); ffma2(acc[3][1], w3, a23);
            ffma2(acc[3][2], w3, a45); ffma2(acc[3][3], w3, a67);
        }
    }

    // ---- Epilogue: write partial -------------------------------------------
    float* part = g_part[kz];
#pragma unroll
    for (int c = 0; c < 4; c++) {
        int co = cg * 4 + c;
        float* ob = &part[(((size_t)b * C_ + co) * H_ + h) * W_ + pg * 8];
        float2 p0 = unpack2(acc[c][0]);
        float2 p1 = unpack2(acc[c][1]);
        float2 p2 = unpack2(acc[c][2]);
        float2 p3 = unpack2(acc[c][3]);
        *(float4*)ob       = make_float4(p0.x, p0.y, p1.x, p1.y);
        *(float4*)(ob + 4) = make_float4(p2.x, p2.y, p3.x, p3.y);
    }
}

// ---------------------------------------------------------------------------
// K3: out = partA + partB
// ---------------------------------------------------------------------------
__global__ __launch_bounds__(256)
void k3_reduce(float* __restrict__ out) {
    const float4* a = (const float4*)g_part[0];
    const float4* bb = (const float4*)g_part[1];
    float4* o = (float4*)out;
    int i = blockIdx.x * 1024 + threadIdx.x;
#pragma unroll
    for (int j = 0; j < 4; j++) {
        int idx = i + j * 256;
        float4 va = a[idx], vb = bb[idx];
        o[idx] = make_float4(va.x + vb.x, va.y + vb.y, va.z + vb.z, va.w + vb.w);
    }
}

// ---------------------------------------------------------------------------
extern "C" void kernel_launch(void* const* d_in, const int* in_sizes, int n_in,
                              void* d_out, int out_size) {
    const float* x     = (const float*)d_in[0];
    const float* Woff  = (const float*)d_in[1];
    const float* boff  = (const float*)d_in[2];
    const float* Wconv = (const float*)d_in[3];
    float* out = (float*)d_out;

    cudaFuncSetAttribute(k1_offset_conv,
                         cudaFuncAttributeMaxDynamicSharedMemorySize, K1_SMEM);
    cudaFuncSetAttribute(k2_sample_gemm,
                         cudaFuncAttributeMaxDynamicSharedMemorySize, K2_SMEM);

    k1_offset_conv<<<dim3(2, 4, 41), 256, K1_SMEM>>>(x, Woff, boff, Wconv);
    k2_sample_gemm<<<dim3(H_, B_, 2), 128, K2_SMEM>>>();
    k3_reduce<<<(B_ * C_ * H_ * W_ / 4) / 1024, 256>>>(out);
}

// round 17
// speedup vs baseline: 1.1445x; 1.1445x over previous
#include <cuda_runtime.h>
#include <cstdint>

#define B_  8
#define C_  64
#define H_  64
#define W_  64
#define NN  9
#define M_  18
#define HP  66
#define KTOT 576

typedef unsigned long long ull;

__device__ float g_off4[4][B_ * M_ * H_ * W_];   // k1 4-way split-k partials
__device__ float g_Wp[KTOT * C_];                // [(n*64+ci)*64 + co]

// ---------------- helpers ----------------
__device__ __forceinline__ void ffma2(ull& d, ull a, ull b) {
    asm("fma.rn.f32x2 %0, %1, %2, %0;" : "+l"(d) : "l"(a), "l"(b));
}
__device__ __forceinline__ float2 unpack2(ull v) {
    float2 r; asm("mov.b64 {%0, %1}, %2;" : "=f"(r.x), "=f"(r.y) : "l"(v)); return r;
}
__device__ __forceinline__ ull dup2(float v) {
    ull r; asm("mov.b64 %0, {%1, %1};" : "=l"(r) : "f"(v)); return r;
}
__device__ __forceinline__ ull pack2(float lo, float hi) {
    ull r; asm("mov.b64 %0, {%1, %2};" : "=l"(r) : "f"(lo), "f"(hi)); return r;
}

// ---------------------------------------------------------------------------
// K1: offset conv, 2 px/thread, 4-way ci split, 128-thr blocks (8h x 32w tile)
// -> 5 blocks/SM, grid 528 fully resident. z = b*4+q; z==32 preps g_Wp.
// ---------------------------------------------------------------------------
#define CI_Q 16
#define K1_SMEM ((CI_Q*340 + CI_Q*9*10*2) * 4)   // 21760 + 11520 = 33280 B

__global__ __launch_bounds__(128, 5)
void k1_offset_conv(const float* __restrict__ x,
                    const float* __restrict__ Woff,
                    const float* __restrict__ boff,
                    const float* __restrict__ Wc) {
    const int tid = threadIdx.x;

    if (blockIdx.z == 32) {      // prep permuted GEMM weights
        int base = (blockIdx.y * 2 + blockIdx.x) * 128 + tid;
        for (int i = base; i < KTOT * C_; i += 16 * 128) {
            int kp = i >> 6;
            int co = i & 63;
            int n  = kp >> 6;
            int ci = kp & 63;
            g_Wp[i] = Wc[co * KTOT + ci * 9 + n];
        }
        return;
    }

    extern __shared__ float smem[];
    float*  xs  = smem;                          // [cil][10][34]
    float2* ws2 = (float2*)(smem + CI_Q * 340);  // [cil][9 j][10 t]

    const int b   = blockIdx.z >> 2;
    const int qf  = blockIdx.z & 3;
    const int ci0 = qf * CI_Q;
    const int th0 = blockIdx.y * 8;
    const int tw0 = blockIdx.x * 32;

    const float* xb = x + (size_t)b * C_ * H_ * W_;
    for (int idx = tid; idx < CI_Q * 340; idx += 128) {
        int cil = idx / 340;
        int rem = idx % 340;
        int r = rem / 34, c = rem % 34;
        int gh = th0 + r - 1, gw = tw0 + c - 1;
        float v = 0.f;
        if ((unsigned)gh < H_ && (unsigned)gw < W_)
            v = xb[((ci0 + cil) * H_ + gh) * W_ + gw];
        xs[idx] = v;
    }
    for (int idx = tid; idx < CI_Q * 81; idx += 128) {
        int cil = idx / 81;
        int rem = idx % 81;
        int j = rem / 9, t = rem % 9;
        int ci = ci0 + cil;
        ws2[(cil * 9 + j) * 10 + t] =
            make_float2(Woff[(2 * j)     * 576 + ci * 9 + t],
                        Woff[(2 * j + 1) * 576 + ci * 9 + t]);
    }
    __syncthreads();

    const int lh = tid >> 4;        // 0..7
    const int lw = tid & 15;        // px pair (2lw, 2lw+1)
    ull acc[9][2];
#pragma unroll
    for (int j = 0; j < 9; j++) {
        ull init = (qf == 0) ? pack2(boff[2 * j], boff[2 * j + 1]) : 0ull;
        acc[j][0] = init;
        acc[j][1] = init;
    }

    for (int cil = 0; cil < CI_Q; cil++) {
        ull d[3][4];
        const float* xc = xs + cil * 340 + lh * 34 + 2 * lw;
#pragma unroll
        for (int u = 0; u < 3; u++) {
            float2 A = *(const float2*)(xc + u * 34);
            float2 Bv = *(const float2*)(xc + u * 34 + 2);
            d[u][0] = dup2(A.x);
            d[u][1] = dup2(A.y);
            d[u][2] = dup2(Bv.x);
            d[u][3] = dup2(Bv.y);
        }
#pragma unroll
        for (int j = 0; j < 9; j++) {
            const ulonglong2* wp = (const ulonglong2*)(ws2 + (cil * 9 + j) * 10);
            ulonglong2 wA = wp[0];
            ulonglong2 wB = wp[1];
            ulonglong2 wC = wp[2];
            ulonglong2 wD = wp[3];
            ull        wE = *(const ull*)(ws2 + (cil * 9 + j) * 10 + 8);
            ffma2(acc[j][0], wA.x, d[0][0]); ffma2(acc[j][1], wA.x, d[0][1]);
            ffma2(acc[j][0], wA.y, d[0][1]); ffma2(acc[j][1], wA.y, d[0][2]);
            ffma2(acc[j][0], wB.x, d[0][2]); ffma2(acc[j][1], wB.x, d[0][3]);
            ffma2(acc[j][0], wB.y, d[1][0]); ffma2(acc[j][1], wB.y, d[1][1]);
            ffma2(acc[j][0], wC.x, d[1][1]); ffma2(acc[j][1], wC.x, d[1][2]);
            ffma2(acc[j][0], wC.y, d[1][2]); ffma2(acc[j][1], wC.y, d[1][3]);
            ffma2(acc[j][0], wD.x, d[2][0]); ffma2(acc[j][1], wD.x, d[2][1]);
            ffma2(acc[j][0], wD.y, d[2][1]); ffma2(acc[j][1], wD.y, d[2][2]);
            ffma2(acc[j][0], wE,   d[2][2]); ffma2(acc[j][1], wE,   d[2][3]);
        }
    }

    const int h = th0 + lh, w0 = tw0 + 2 * lw;
    float* dst = g_off4[qf];
#pragma unroll
    for (int j = 0; j < 9; j++) {
        float2 p0 = unpack2(acc[j][0]);
        float2 p1 = unpack2(acc[j][1]);
        *(float2*)&dst[((b * M_ + 2 * j)     * H_ + h) * W_ + w0] = make_float2(p0.x, p1.x);
        *(float2*)&dst[((b * M_ + 2 * j + 1) * H_ + h) * W_ + w0] = make_float2(p0.y, p1.y);
    }
}

// ---------------------------------------------------------------------------
// K2: fused bilinear sampling + GEMM (R11/R15-proven form).
// Block = (b, 1 row) = 64 px, 128 thr. 18 chunks of 32 k-rows (k = n*64+ci).
// ---------------------------------------------------------------------------
#define NSAMP 576
#define CK    32
#define SM_Q  0                                  // ushort4[576] = 4608
#define SM_G  (SM_Q + NSAMP * 8)                 // float4[576]  = 9216
#define SM_XO (SM_G + NSAMP * 16)                // [32][64] = 8192
#define SM_W  (SM_XO + CK * 64 * 4)              // [32][64] = 8192
#define K2_SMEM (SM_W + CK * 64 * 4)             // 30208

__global__ __launch_bounds__(128, 5)
void k2_sample_gemm(const float* __restrict__ x, float* __restrict__ out) {
    extern __shared__ char smc[];
    ushort4* s_q  = (ushort4*)(smc + SM_Q);
    float4*  s_g  = (float4*)(smc + SM_G);
    float*   xo_s = (float*)(smc + SM_XO);
    float*   w_s  = (float*)(smc + SM_W);

    const int tid = threadIdx.x;
    const int h   = blockIdx.x;
    const int b   = blockIdx.y;

    // ---- Phase A: 4 clamped element-offsets + pre-zeroed weights -----------
    for (int t = tid; t < NSAMP; t += 128) {
        int n  = t >> 6;
        int px = t & 63;
        int ixi = ((b * M_ + n)     * H_ + h) * W_ + px;
        int iyi = ((b * M_ + 9 + n) * H_ + h) * W_ + px;
        float offx = (g_off4[0][ixi] + g_off4[1][ixi])
                   + (g_off4[2][ixi] + g_off4[3][ixi]);
        float offy = (g_off4[0][iyi] + g_off4[1][iyi])
                   + (g_off4[2][iyi] + g_off4[3][iyi]);
        float pX = (float)(h + 1)  + (float)(n / 3 - 1) + offx;
        float pY = (float)(px + 1) + (float)(n % 3 - 1) + offy;
        float fx = floorf(pX), fy = floorf(pY);
        int x0 = min(max((int)fx,     0), HP - 1);
        int x1 = min(max((int)fx + 1, 0), HP - 1);
        int y0 = min(max((int)fy,     0), HP - 1);
        int y1 = min(max((int)fy + 1, 0), HP - 1);
        float pxc = fminf(fmaxf(pX, 0.f), (float)(HP - 1));
        float pyc = fminf(fmaxf(pY, 0.f), (float)(HP - 1));
        float gx0 = 1.f + ((float)x0 - pxc);
        float gx1 = 1.f - ((float)x1 - pxc);
        float gy0 = 1.f + ((float)y0 - pyc);
        float gy1 = 1.f - ((float)y1 - pyc);
        int ix0 = x0 - 1, iy0 = y0 - 1, ix1 = x1 - 1, iy1 = y1 - 1;
        bool vx0 = (unsigned)ix0 < H_, vy0 = (unsigned)iy0 < W_;
        bool vx1 = (unsigned)ix1 < H_, vy1 = (unsigned)iy1 < W_;
        int cx0 = min(max(ix0, 0), H_ - 1);
        int cx1 = min(max(ix1, 0), H_ - 1);
        int cy0 = min(max(iy0, 0), W_ - 1);
        int cy1 = min(max(iy1, 0), W_ - 1);
        s_q[t] = make_ushort4((unsigned short)((cx0 << 6) + cy0),
                              (unsigned short)((cx1 << 6) + cy1),
                              (unsigned short)((cx0 << 6) + cy1),
                              (unsigned short)((cx1 << 6) + cy0));
        s_g[t] = make_float4(vx0 && vy0 ? gx0 * gy0 : 0.f,
                             vx1 && vy1 ? gx1 * gy1 : 0.f,
                             vx0 && vy1 ? gx0 * gy1 : 0.f,
                             vx1 && vy0 ? gx1 * gy0 : 0.f);
    }

    const int px   = tid & 63;
    const int half = tid >> 6;
    const int pg   = tid >> 4;
    const int cg   = tid & 15;
    const float* xbase = x + (size_t)b * C_ * H_ * W_;

    ull acc[4][4];
#pragma unroll
    for (int i = 0; i < 4; i++)
#pragma unroll
        for (int j = 0; j < 4; j++) acc[i][j] = 0ull;

    for (int c = 0; c < 18; c++) {
        const int n   = c >> 1;
        const int ci0 = (c & 1) * 32;
        __syncthreads();

        // B chunk
        {
            const float4* src = (const float4*)(g_Wp + c * (CK * 64));
            float4* dst = (float4*)w_s;
#pragma unroll
            for (int j = 0; j < 4; j++)
                dst[j * 128 + tid] = src[j * 128 + tid];
        }

        // gather: meta once, 16 ci per thread
        {
            ushort4 q = s_q[n * 64 + px];
            float4  g = s_g[n * 64 + px];
#pragma unroll 4
            for (int i = 0; i < 16; i++) {
                int lk = half * 16 + i;
                int ci = ci0 + lk;
                const float* xc = xbase + (ci << 12);
                float v = g.x * __ldg(xc + q.x) + g.y * __ldg(xc + q.y)
                        + g.z * __ldg(xc + q.z) + g.w * __ldg(xc + q.w);
                xo_s[lk * 64 + px] = v;
            }
        }
        __syncthreads();

        // GEMM chunk: 32 kk, 16 FFMA2/kk
#pragma unroll 4
        for (int kk = 0; kk < CK; kk++) {
            float4 a0 = *(const float4*)&xo_s[kk * 64 + pg * 8];
            float4 a1 = *(const float4*)&xo_s[kk * 64 + pg * 8 + 4];
            float4 w  = *(const float4*)&w_s[kk * 64 + cg * 4];
            ull a01 = ((const ull*)&a0)[0];
            ull a23 = ((const ull*)&a0)[1];
            ull a45 = ((const ull*)&a1)[0];
            ull a67 = ((const ull*)&a1)[1];
            ull w0 = dup2(w.x), w1 = dup2(w.y), w2 = dup2(w.z), w3 = dup2(w.w);
            ffma2(acc[0][0], w0, a01); ffma2(acc[0][1], w0, a23);
            ffma2(acc[0][2], w0, a45); ffma2(acc[0][3], w0, a67);
            ffma2(acc[1][0], w1, a01); ffma2(acc[1][1], w1, a23);
            ffma2(acc[1][2], w1, a45); ffma2(acc[1][3], w1, a67);
            ffma2(acc[2][0], w2, a01); ffma2(acc[2][1], w2, a23);
            ffma2(acc[2][2], w2, a45); ffma2(acc[2][3], w2, a67);
            ffma2(acc[3][0], w3, a01); ffma2(acc[3][1], w3, a23);
            ffma2(acc[3][2], w3, a45); ffma2(acc[3][3], w3, a67);
        }
    }

    // ---- Epilogue ----------------------------------------------------------
#pragma unroll
    for (int c = 0; c < 4; c++) {
        int co = cg * 4 + c;
        float* ob = &out[(((size_t)b * C_ + co) * H_ + h) * W_ + pg * 8];
        float2 p0 = unpack2(acc[c][0]);
        float2 p1 = unpack2(acc[c][1]);
        float2 p2 = unpack2(acc[c][2]);
        float2 p3 = unpack2(acc[c][3]);
        *(float4*)ob       = make_float4(p0.x, p0.y, p1.x, p1.y);
        *(float4*)(ob + 4) = make_float4(p2.x, p2.y, p3.x, p3.y);
    }
}

// ---------------------------------------------------------------------------
extern "C" void kernel_launch(void* const* d_in, const int* in_sizes, int n_in,
                              void* d_out, int out_size) {
    const float* x     = (const float*)d_in[0];
    const float* Woff  = (const float*)d_in[1];
    const float* boff  = (const float*)d_in[2];
    const float* Wconv = (const float*)d_in[3];
    float* out = (float*)d_out;

    cudaFuncSetAttribute(k1_offset_conv,
                         cudaFuncAttributeMaxDynamicSharedMemorySize, K1_SMEM);
    cudaFuncSetAttribute(k2_sample_gemm,
                         cudaFuncAttributeMaxDynamicSharedMemorySize, K2_SMEM);

    k1_offset_conv<<<dim3(2, 8, 33), 128, K1_SMEM>>>(x, Woff, boff, Wconv);
    k2_sample_gemm<<<dim3(H_, B_), 128, K2_SMEM>>>(x, out);
}